// round 2
// baseline (speedup 1.0000x reference)
#include <cuda_runtime.h>
#include <cuda_fp16.h>
#include <cstdint>

static constexpr int BATCH = 65536;
static constexpr int KD    = 512;
static constexpr int ND    = 512;

static constexpr int BM = 128;
static constexpr int BN = 128;
static constexpr int BK = 32;
static constexpr int NKITER = KD / BK;   // 16

// smem tile: 128 rows x 32 fp16 cols = 128 x 64B rows, XOR-swizzled at 16B grain.
// element (r, k): byte = r*64 + ((k>>3) ^ ((r>>1)&3))*16 + (k&7)*2
static __device__ __forceinline__ uint32_t smem_u32(const void* p) {
    uint32_t a;
    asm("{ .reg .u64 t; cvta.to.shared.u64 t, %1; cvt.u32.u64 %0, t; }"
        : "=r"(a) : "l"(p));
    return a;
}

__device__ __forceinline__ void ldsm4(uint32_t& r0, uint32_t& r1, uint32_t& r2,
                                      uint32_t& r3, uint32_t addr) {
    asm volatile("ldmatrix.sync.aligned.m8n8.x4.shared.b16 {%0,%1,%2,%3}, [%4];"
                 : "=r"(r0), "=r"(r1), "=r"(r2), "=r"(r3) : "r"(addr));
}

__device__ __forceinline__ void mma16816(float* d, const uint32_t* a, const uint32_t* b) {
    asm volatile(
        "mma.sync.aligned.m16n8k16.row.col.f32.f16.f16.f32 "
        "{%0,%1,%2,%3}, {%4,%5,%6,%7}, {%8,%9}, {%0,%1,%2,%3};"
        : "+f"(d[0]), "+f"(d[1]), "+f"(d[2]), "+f"(d[3])
        : "r"(a[0]), "r"(a[1]), "r"(a[2]), "r"(a[3]), "r"(b[0]), "r"(b[1]));
}

// store 4 fp32 -> 4 fp16 (8B) into swizzled tile; q = 8B-unit index (0..7) in the row
__device__ __forceinline__ void sts_cvt(char* buf, int r, int q, float4 v) {
    __half2 h0 = __floats2half2_rn(v.x, v.y);
    __half2 h1 = __floats2half2_rn(v.z, v.w);
    uint2 u;
    u.x = *reinterpret_cast<uint32_t*>(&h0);
    u.y = *reinterpret_cast<uint32_t*>(&h1);
    uint32_t off = (uint32_t)(r * 64 + (((q >> 1) ^ ((r >> 1) & 3)) << 4) + ((q & 1) << 3));
    *reinterpret_cast<uint2*>(buf + off) = u;
}

// ldmatrix source address for (row = base_r + (lane&15), chunk = ks*2 + (lane>>4))
__device__ __forceinline__ uint32_t ldsm_addr(uint32_t sbase, int base_r, int ks, int lane) {
    int r = base_r + (lane & 15);
    int c = ks * 2 + (lane >> 4);
    return sbase + (uint32_t)(r * 64 + ((c ^ ((r >> 1) & 3)) << 4));
}

__global__ void __launch_bounds__(256, 1)
gemm_f16_kernel(const float* __restrict__ X, const float* __restrict__ W,
                const float* __restrict__ Bv, float* __restrict__ Y) {
    __shared__ __align__(1024) char sA[2][BM * 64];
    __shared__ __align__(1024) char sB[2][BN * 64];

    const int tid  = threadIdx.x;
    const int wid  = tid >> 5;
    const int lane = tid & 31;

    const int bm = blockIdx.x >> 2;
    const int bn = blockIdx.x & 3;
    const int row0 = bm * BM;
    const int col0 = bn * BN;

    const float* Ax = X + (size_t)row0 * KD;
    const float* Bw = W + (size_t)col0 * KD;

    const int lr = tid >> 3;   // 0..31 (row within 32-row slab)
    const int lq = tid & 7;    // 0..7  (float4 quad within 32-col row)

    float acc[4][4][4];
#pragma unroll
    for (int i = 0; i < 4; i++)
#pragma unroll
        for (int j = 0; j < 4; j++)
#pragma unroll
            for (int e = 0; e < 4; e++) acc[i][j][e] = 0.0f;

    // ---- prologue: load K-chunk 0 and stage into buffer 0 ----
    float4 ra[4], rb[4];
#pragma unroll
    for (int i = 0; i < 4; i++) {
        ra[i] = *reinterpret_cast<const float4*>(Ax + (size_t)(lr + 32 * i) * KD + lq * 4);
        rb[i] = *reinterpret_cast<const float4*>(Bw + (size_t)(lr + 32 * i) * KD + lq * 4);
    }
#pragma unroll
    for (int i = 0; i < 4; i++) {
        sts_cvt(sA[0], lr + 32 * i, lq, ra[i]);
        sts_cvt(sB[0], lr + 32 * i, lq, rb[i]);
    }
    __syncthreads();

    const int wm = wid & 1;    // 0..1 -> M offset 0/64
    const int wn = wid >> 1;   // 0..3 -> N offset 0/32/64/96
    const int a_row0 = wm * 64;
    const int b_row0 = wn * 32;

    for (int kt = 0; kt < NKITER; kt++) {
        const int cur = kt & 1;

        // prefetch next K-chunk from gmem (latency hidden behind compute)
        if (kt + 1 < NKITER) {
            const int kb = (kt + 1) * BK + lq * 4;
#pragma unroll
            for (int i = 0; i < 4; i++) {
                ra[i] = *reinterpret_cast<const float4*>(Ax + (size_t)(lr + 32 * i) * KD + kb);
                rb[i] = *reinterpret_cast<const float4*>(Bw + (size_t)(lr + 32 * i) * KD + kb);
            }
        }

        // ---- compute on buffer cur ----
        const uint32_t a_sb = smem_u32(sA[cur]);
        const uint32_t b_sb = smem_u32(sB[cur]);
#pragma unroll
        for (int ks = 0; ks < 2; ks++) {
            uint32_t af[4][4];
            uint32_t bf[2][4];   // [n-pair][4 regs] -> n-tiles (2p, 2p+1)
#pragma unroll
            for (int mt = 0; mt < 4; mt++)
                ldsm4(af[mt][0], af[mt][1], af[mt][2], af[mt][3],
                      ldsm_addr(a_sb, a_row0 + mt * 16, ks, lane));
#pragma unroll
            for (int np = 0; np < 2; np++)
                ldsm4(bf[np][0], bf[np][1], bf[np][2], bf[np][3],
                      ldsm_addr(b_sb, b_row0 + np * 16, ks, lane));
#pragma unroll
            for (int mt = 0; mt < 4; mt++) {
#pragma unroll
                for (int nt = 0; nt < 4; nt++) {
                    uint32_t bb[2] = { bf[nt >> 1][(nt & 1)],
                                       bf[nt >> 1][(nt & 1) + 2] };
                    mma16816(acc[mt][nt], af[mt], bb);
                }
            }
        }

        // ---- stage next chunk into the other buffer ----
        if (kt + 1 < NKITER) {
            const int nxt = cur ^ 1;
#pragma unroll
            for (int i = 0; i < 4; i++) {
                sts_cvt(sA[nxt], lr + 32 * i, lq, ra[i]);
                sts_cvt(sB[nxt], lr + 32 * i, lq, rb[i]);
            }
            __syncthreads();
        }
    }

    // ---- epilogue: add bias, store fp32 ----
    const int crow = row0 + wm * 64;
    const int ccol = col0 + wn * 32;
#pragma unroll
    for (int nt = 0; nt < 4; nt++) {
        const int c = ccol + nt * 8 + (lane & 3) * 2;
        const float2 bv = *reinterpret_cast<const float2*>(Bv + c);
#pragma unroll
        for (int mt = 0; mt < 4; mt++) {
            const int r = crow + mt * 16 + (lane >> 2);
            float2 v0, v1;
            v0.x = acc[mt][nt][0] + bv.x;
            v0.y = acc[mt][nt][1] + bv.y;
            v1.x = acc[mt][nt][2] + bv.x;
            v1.y = acc[mt][nt][3] + bv.y;
            *reinterpret_cast<float2*>(Y + (size_t)r * ND + c) = v0;
            *reinterpret_cast<float2*>(Y + (size_t)(r + 8) * ND + c) = v1;
        }
    }
}

extern "C" void kernel_launch(void* const* d_in, const int* in_sizes, int n_in,
                              void* d_out, int out_size) {
    const float* x = nullptr;
    const float* w = nullptr;
    const float* b = nullptr;
    for (int i = 0; i < n_in; i++) {
        if (in_sizes[i] == BATCH * KD)   x = (const float*)d_in[i];
        else if (in_sizes[i] == ND * KD) w = (const float*)d_in[i];
        else if (in_sizes[i] == ND)      b = (const float*)d_in[i];
    }
    float* out = (float*)d_out;

    const int grid = (BATCH / BM) * (ND / BN);   // 512 * 4 = 2048
    gemm_f16_kernel<<<grid, 256>>>(x, w, b, out);
}

// round 4
// speedup vs baseline: 1.4014x; 1.4014x over previous
#include <cuda_runtime.h>
#include <cuda_fp16.h>
#include <cstdint>

static constexpr int BATCH = 65536;
static constexpr int KD    = 512;
static constexpr int ND    = 512;

static constexpr int BM = 128;
static constexpr int BN = 128;
static constexpr int BK = 64;          // 64 fp16 = 128B rows
static constexpr int NKITER = KD / BK; // 8
static constexpr int STAGES = 3;
static constexpr int TILE_BYTES = BM * 128;             // 16 KB (A or B)
static constexpr int STAGE_BYTES = 2 * TILE_BYTES;      // 32 KB
static constexpr int SMEM_TOTAL = STAGES * STAGE_BYTES; // 96 KB

// ---------------- fp16 scratch (no allocs allowed) ----------------
__device__ __align__(256) __half g_xh[(size_t)BATCH * KD];
__device__ __align__(256) __half g_wh[ND * KD];

// ---------------- helpers ----------------
static __device__ __forceinline__ uint32_t smem_u32(const void* p) {
    uint32_t a;
    asm("{ .reg .u64 t; cvta.to.shared.u64 t, %1; cvt.u32.u64 %0, t; }"
        : "=r"(a) : "l"(p));
    return a;
}

__device__ __forceinline__ void cp16(uint32_t dst, const void* src) {
    asm volatile("cp.async.cg.shared.global [%0], [%1], 16;"
                 :: "r"(dst), "l"(src) : "memory");
}
__device__ __forceinline__ void cp_commit() {
    asm volatile("cp.async.commit_group;" ::: "memory");
}
template <int N>
__device__ __forceinline__ void cp_wait() {
    asm volatile("cp.async.wait_group %0;" :: "n"(N) : "memory");
}

__device__ __forceinline__ void ldsm4(uint32_t& r0, uint32_t& r1, uint32_t& r2,
                                      uint32_t& r3, uint32_t addr) {
    asm volatile("ldmatrix.sync.aligned.m8n8.x4.shared.b16 {%0,%1,%2,%3}, [%4];"
                 : "=r"(r0), "=r"(r1), "=r"(r2), "=r"(r3) : "r"(addr));
}

__device__ __forceinline__ void mma16816(float* d, const uint32_t* a, const uint32_t* b) {
    asm volatile(
        "mma.sync.aligned.m16n8k16.row.col.f32.f16.f16.f32 "
        "{%0,%1,%2,%3}, {%4,%5,%6,%7}, {%8,%9}, {%0,%1,%2,%3};"
        : "+f"(d[0]), "+f"(d[1]), "+f"(d[2]), "+f"(d[3])
        : "r"(a[0]), "r"(a[1]), "r"(a[2]), "r"(a[3]), "r"(b[0]), "r"(b[1]));
}

// ---------------- prepass: fp32 -> fp16 (globals referenced in DEVICE code) ----------------
__device__ __forceinline__ void cvt_body(const float* __restrict__ s,
                                         __half* __restrict__ d, size_t i) {
    float4 v = reinterpret_cast<const float4*>(s)[i];
    __half2 h0 = __floats2half2_rn(v.x, v.y);
    __half2 h1 = __floats2half2_rn(v.z, v.w);
    uint2 u;
    u.x = *reinterpret_cast<uint32_t*>(&h0);
    u.y = *reinterpret_cast<uint32_t*>(&h1);
    reinterpret_cast<uint2*>(d)[i] = u;
}

__global__ void __launch_bounds__(256) cvt_x_kernel(const float* __restrict__ s) {
    size_t i = (size_t)blockIdx.x * 256 + threadIdx.x;
    cvt_body(s, g_xh, i);
}

__global__ void __launch_bounds__(256) cvt_w_kernel(const float* __restrict__ s) {
    size_t i = (size_t)blockIdx.x * 256 + threadIdx.x;
    cvt_body(s, g_wh, i);
}

// ---------------- GEMM ----------------
// smem tile: 128 rows x 128B. elem (r, 16B-chunk c): byte = r*128 + ((c ^ (r&7))<<4)
__global__ void __launch_bounds__(256, 2)
gemm_f16_kernel(const float* __restrict__ Bv, float* __restrict__ Y) {
    extern __shared__ __align__(1024) char smem[];
    const uint32_t sb = smem_u32(smem);

    const int tid  = threadIdx.x;
    const int wid  = tid >> 5;
    const int lane = tid & 31;

    const int bm = blockIdx.x >> 2;
    const int bn = blockIdx.x & 3;
    const int row0 = bm * BM;
    const int col0 = bn * BN;

    // cp.async staging geometry: thread -> (row sr [+32i], 16B chunk sc)
    const int sr = tid >> 3;
    const int sc = tid & 7;
    const uint32_t sdst = (uint32_t)(sr * 128 + (((uint32_t)sc << 4) ^ ((uint32_t)(sr & 7) << 4)));
    const __half* Asrc0 = g_xh + (size_t)(row0 + sr) * KD + sc * 8;
    const __half* Bsrc0 = g_wh + (size_t)(col0 + sr) * KD + sc * 8;

    // ldmatrix addressing: row XOR term == (lane&7)<<4 for all fragments
    const int wm = wid & 1;     // M offset 0/64
    const int wn = wid >> 1;    // N offset 0/32/64/96
    const uint32_t sw  = (uint32_t)((lane & 7) << 4);
    const uint32_t c16 = (uint32_t)((lane >> 4) << 4);  // 0 or 16
    uint32_t aRow[4], bRow[2], kx[4];
#pragma unroll
    for (int mt = 0; mt < 4; mt++)
        aRow[mt] = (uint32_t)((wm * 64 + mt * 16 + (lane & 15)) * 128);
#pragma unroll
    for (int np = 0; np < 2; np++)
        bRow[np] = (uint32_t)((wn * 32 + np * 16 + (lane & 15)) * 128);
#pragma unroll
    for (int ks = 0; ks < 4; ks++)
        kx[ks] = (uint32_t)(ks * 32 + c16) ^ sw;

    float acc[4][4][4];
#pragma unroll
    for (int i = 0; i < 4; i++)
#pragma unroll
        for (int j = 0; j < 4; j++)
#pragma unroll
            for (int e = 0; e < 4; e++) acc[i][j][e] = 0.0f;

    auto stage = [&](int kt, int slot) {
        const uint32_t base = sb + slot * STAGE_BYTES + sdst;
        const __half* as = Asrc0 + kt * BK;
        const __half* bs = Bsrc0 + kt * BK;
#pragma unroll
        for (int i = 0; i < 4; i++)
            cp16(base + i * (32 * 128), as + (size_t)(32 * i) * KD);
#pragma unroll
        for (int i = 0; i < 4; i++)
            cp16(base + TILE_BYTES + i * (32 * 128), bs + (size_t)(32 * i) * KD);
    };

    stage(0, 0); cp_commit();
    stage(1, 1); cp_commit();

    for (int kt = 0; kt < NKITER; kt++) {
        cp_wait<1>();
        __syncthreads();
        if (kt + 2 < NKITER) stage(kt + 2, (kt + 2) % STAGES);
        cp_commit();

        const uint32_t abase = sb + (kt % STAGES) * STAGE_BYTES;
        const uint32_t bbase = abase + TILE_BYTES;
#pragma unroll
        for (int ks = 0; ks < 4; ks++) {
            uint32_t af[4][4], bf[2][4];
#pragma unroll
            for (int mt = 0; mt < 4; mt++)
                ldsm4(af[mt][0], af[mt][1], af[mt][2], af[mt][3],
                      abase + aRow[mt] + kx[ks]);
#pragma unroll
            for (int np = 0; np < 2; np++)
                ldsm4(bf[np][0], bf[np][1], bf[np][2], bf[np][3],
                      bbase + bRow[np] + kx[ks]);
#pragma unroll
            for (int mt = 0; mt < 4; mt++) {
#pragma unroll
                for (int nt = 0; nt < 4; nt++) {
                    uint32_t bb[2] = { bf[nt >> 1][(nt & 1)],
                                       bf[nt >> 1][(nt & 1) + 2] };
                    mma16816(acc[mt][nt], af[mt], bb);
                }
            }
        }
    }

    // epilogue: bias + fp32 store
    const int crow = row0 + wm * 64;
    const int ccol = col0 + wn * 32;
#pragma unroll
    for (int nt = 0; nt < 4; nt++) {
        const int c = ccol + nt * 8 + (lane & 3) * 2;
        const float2 bv = *reinterpret_cast<const float2*>(Bv + c);
#pragma unroll
        for (int mt = 0; mt < 4; mt++) {
            const int r = crow + mt * 16 + (lane >> 2);
            float2 v0, v1;
            v0.x = acc[mt][nt][0] + bv.x;
            v0.y = acc[mt][nt][1] + bv.y;
            v1.x = acc[mt][nt][2] + bv.x;
            v1.y = acc[mt][nt][3] + bv.y;
            *reinterpret_cast<float2*>(Y + (size_t)r * ND + c) = v0;
            *reinterpret_cast<float2*>(Y + (size_t)(r + 8) * ND + c) = v1;
        }
    }
}

extern "C" void kernel_launch(void* const* d_in, const int* in_sizes, int n_in,
                              void* d_out, int out_size) {
    const float* x = nullptr;
    const float* w = nullptr;
    const float* b = nullptr;
    for (int i = 0; i < n_in; i++) {
        if (in_sizes[i] == BATCH * KD)   x = (const float*)d_in[i];
        else if (in_sizes[i] == ND * KD) w = (const float*)d_in[i];
        else if (in_sizes[i] == ND)      b = (const float*)d_in[i];
    }
    float* out = (float*)d_out;

    cvt_x_kernel<<<(BATCH * KD / 4) / 256, 256>>>(x);   // 32768 blocks
    cvt_w_kernel<<<(ND * KD / 4) / 256, 256>>>(w);      // 256 blocks

    cudaFuncSetAttribute(gemm_f16_kernel,
                         cudaFuncAttributeMaxDynamicSharedMemorySize, SMEM_TOTAL);
    gemm_f16_kernel<<<(BATCH / BM) * (ND / BN), 256, SMEM_TOTAL>>>(b, out);
}